// round 6
// baseline (speedup 1.0000x reference)
#include <cuda_runtime.h>
#include <cuda_fp16.h>
#include <cstdint>

#define N_USERS 100000
#define N_ITEMS 50000
#define N_NODES (N_USERS + N_ITEMS)   // 150000
#define D 64
#define DH2 (D / 4)                   // 16 uint2 (4 halves each) per row
#define MAX_E 4000000

#define SCAN_BLK  1024
#define SCAN_TILE (SCAN_BLK * 4)                           // 4096
#define SCAN_NB   ((N_ITEMS + SCAN_TILE - 1) / SCAN_TILE)  // 13

// ---------------- static device scratch -------------------------------------
__device__ int   g_count[(N_ITEMS + 3) & ~3];
__device__ int   g_wcur [N_ITEMS];
__device__ int   g_ptr  [N_NODES + 1];
__device__ int   g_bsum [SCAN_NB];
__device__ int2  g_edge [MAX_E];                       // {col, val bits}
__device__ uint2 g_emb_h[(size_t)N_NODES * DH2];       // embeds as fp16
__device__ uint2 g_c1   [(size_t)N_NODES * DH2];       // layer-1 out (fp16)
__device__ uint2 g_c2   [(size_t)N_NODES * DH2];       // layer-2 out (fp16)

// ---------------- build step 1: zero counts + user ptrs (binary search) -----
__global__ void init_kernel(const int* __restrict__ rows, int E2) {
    int idx = blockIdx.x * blockDim.x + threadIdx.x;
    if (idx < N_ITEMS) g_count[idx] = 0;
    int r = idx - N_ITEMS;
    if (r >= 0 && r < N_USERS) {
        int lo = 0, hi = E2;
        while (lo < hi) {
            int m = (lo + hi) >> 1;
            if (rows[m] < r) lo = m + 1; else hi = m;
        }
        g_ptr[r] = lo;
    }
}

// ---------------- convert embeds fp32 -> fp16 --------------------------------
__global__ void convert_kernel(const float* __restrict__ embeds) {
    int i = blockIdx.x * blockDim.x + threadIdx.x;
    if (i >= N_NODES * DH2) return;
    float4 f = ((const float4*)embeds)[i];
    __half2 h0 = __floats2half2_rn(f.x, f.y);
    __half2 h1 = __floats2half2_rn(f.z, f.w);
    uint2 u;
    u.x = *(const unsigned*)&h0;
    u.y = *(const unsigned*)&h1;
    g_emb_h[i] = u;
}

// ---------------- build step 2: histogram (item half) + pack (user half) ----
__global__ void hist_pack_kernel(const int* __restrict__ rows,
                                 const int* __restrict__ cols,
                                 const float* __restrict__ vals, int E) {
    int i = blockIdx.x * blockDim.x + threadIdx.x;
    if (i >= E) return;
    int E2 = E >> 1;
    if (i < E2) {
        g_edge[i] = make_int2(cols[i], __float_as_int(vals[i]));
    } else {
        atomicAdd(&g_count[rows[i] - N_USERS], 1);
    }
}

// ---------------- build step 3a: per-block local exclusive scan -------------
__global__ void scanA_kernel() {
    __shared__ int wsum[32];
    const int tid  = threadIdx.x;
    const int lane = tid & 31;
    const int wid  = tid >> 5;
    int base = blockIdx.x * SCAN_TILE + tid * 4;

    int4 v = make_int4(0, 0, 0, 0);
    if (base < N_ITEMS) v = *(const int4*)&g_count[base];  // g_count padded to mult of 4, zeroed tail
    // guard tail beyond N_ITEMS (padding region is zeroed below in init path)
    if (base + 1 >= N_ITEMS) v.y = 0;
    if (base + 2 >= N_ITEMS) v.z = 0;
    if (base + 3 >= N_ITEMS) v.w = 0;
    if (base >= N_ITEMS) v.x = 0;

    int t = v.x + v.y + v.z + v.w;
    int x = t;
    #pragma unroll
    for (int o = 1; o < 32; o <<= 1) {
        int y = __shfl_up_sync(0xffffffffu, x, o);
        if (lane >= o) x += y;
    }
    if (lane == 31) wsum[wid] = x;
    __syncthreads();
    if (wid == 0) {
        int w = wsum[lane];
        int xs = w;
        #pragma unroll
        for (int o = 1; o < 32; o <<= 1) {
            int y = __shfl_up_sync(0xffffffffu, xs, o);
            if (lane >= o) xs += y;
        }
        wsum[lane] = xs - w;
    }
    __syncthreads();
    int excl = (x - t) + wsum[wid];

    int e0 = excl;
    int e1 = e0 + v.x;
    int e2 = e1 + v.y;
    int e3 = e2 + v.z;
    if (base < N_ITEMS) {
        // write local (block-relative) exclusive scan into g_ptr slots
        int lim = N_ITEMS - base;
        int* p = &g_ptr[N_USERS + base];
        if (lim > 0) p[0] = e0;
        if (lim > 1) p[1] = e1;
        if (lim > 2) p[2] = e2;
        if (lim > 3) p[3] = e3;
    }
    if (tid == SCAN_BLK - 1) g_bsum[blockIdx.x] = e3 + v.w;  // block total
}

// ---------------- build step 3b: scan the block totals (one warp) -----------
__global__ void scanB_kernel(int E2) {
    int lane = threadIdx.x;
    int v = (lane < SCAN_NB) ? g_bsum[lane] : 0;
    int x = v;
    #pragma unroll
    for (int o = 1; o < 32; o <<= 1) {
        int y = __shfl_up_sync(0xffffffffu, x, o);
        if (lane >= o) x += y;
    }
    if (lane < SCAN_NB) g_bsum[lane] = E2 + (x - v);   // exclusive + base
    if (lane == 31) g_ptr[N_NODES] = E2 + x;           // total == E
}

// ---------------- build step 3c: apply block offsets + mirror to wcur -------
__global__ void scanC_kernel() {
    int i4 = (blockIdx.x * blockDim.x + threadIdx.x) * 4;
    if (i4 >= N_ITEMS) return;
    int off = g_bsum[i4 / SCAN_TILE];
    int lim = N_ITEMS - i4;
    int* p = &g_ptr[N_USERS + i4];
    #pragma unroll
    for (int k = 0; k < 4; k++) {
        if (k < lim) {
            int val = p[k] + off;
            p[k] = val;
            g_wcur[i4 + k] = val;
        }
    }
}

// ---------------- build step 4: scatter item-half edges ---------------------
__global__ void scatter_kernel(const int* __restrict__ rows,
                               const int* __restrict__ cols,
                               const float* __restrict__ vals, int E) {
    int i = (blockIdx.x * blockDim.x + threadIdx.x) + (E >> 1);
    if (i >= E) return;
    int j = rows[i] - N_USERS;
    int p = atomicAdd(&g_wcur[j], 1);
    g_edge[p] = make_int2(cols[i], __float_as_int(vals[i]));
}

// ---------------- SpMM (fp16 src -> fp32 accum -> fp16 dst) -----------------
__device__ __forceinline__ void fma4(float2& s01, float2& s23, float v, uint2 x) {
    __half2 h0 = *(const __half2*)&x.x;
    __half2 h1 = *(const __half2*)&x.y;
    float2 f0 = __half22float2(h0);
    float2 f1 = __half22float2(h1);
    s01.x += v * f0.x; s01.y += v * f0.y;
    s23.x += v * f1.x; s23.y += v * f1.y;
}

template <int LAYER>   // 0: emb_h -> c1,  1: c1 -> c2
__global__ void spmm_kernel() {
    int hw = (blockIdx.x * blockDim.x + threadIdx.x) >> 4;
    int ln = threadIdx.x & 15;
    if (hw >= N_NODES) return;

    const uint2* __restrict__ src = (LAYER == 0) ? g_emb_h : g_c1;
    uint2* __restrict__ dst       = (LAYER == 0) ? g_c1    : g_c2;

    int beg = g_ptr[hw];
    int end = g_ptr[hw + 1];

    float2 s01 = make_float2(0.f, 0.f);
    float2 s23 = make_float2(0.f, 0.f);
    int e = beg;
    for (; e + 1 < end; e += 2) {
        int2 a = g_edge[e];
        int2 b = g_edge[e + 1];
        uint2 xa = src[(size_t)a.x * DH2 + ln];
        uint2 xb = src[(size_t)b.x * DH2 + ln];
        fma4(s01, s23, __int_as_float(a.y), xa);
        fma4(s01, s23, __int_as_float(b.y), xb);
    }
    if (e < end) {
        int2 a = g_edge[e];
        uint2 xa = src[(size_t)a.x * DH2 + ln];
        fma4(s01, s23, __int_as_float(a.y), xa);
    }

    __half2 h0 = __floats2half2_rn(s01.x, s01.y);
    __half2 h1 = __floats2half2_rn(s23.x, s23.y);
    uint2 u;
    u.x = *(const unsigned*)&h0;
    u.y = *(const unsigned*)&h1;
    dst[(size_t)hw * DH2 + ln] = u;
}

// ---------------- fused layer-3 SpMM + final gather -------------------------
__global__ void final_kernel(const float* __restrict__ embeds,
                             const int* __restrict__ users,
                             const int* __restrict__ pos,
                             const int* __restrict__ neg,
                             float4* __restrict__ out, int B) {
    int row = (blockIdx.x * blockDim.x + threadIdx.x) >> 4;
    int ln  = threadIdx.x & 15;
    if (row >= 3 * B) return;
    int grp = row / B;
    int r   = row - grp * B;
    int n;
    if (grp == 0)      n = users[r];
    else if (grp == 1) n = pos[r] + N_USERS;
    else               n = neg[r] + N_USERS;

    int beg = g_ptr[n];
    int end = g_ptr[n + 1];
    float2 s01 = make_float2(0.f, 0.f);
    float2 s23 = make_float2(0.f, 0.f);
    int e = beg;
    for (; e + 1 < end; e += 2) {
        int2 a = g_edge[e];
        int2 b = g_edge[e + 1];
        uint2 xa = g_c2[(size_t)a.x * DH2 + ln];
        uint2 xb = g_c2[(size_t)b.x * DH2 + ln];
        fma4(s01, s23, __int_as_float(a.y), xa);
        fma4(s01, s23, __int_as_float(b.y), xb);
    }
    if (e < end) {
        int2 a = g_edge[e];
        uint2 xa = g_c2[(size_t)a.x * DH2 + ln];
        fma4(s01, s23, __int_as_float(a.y), xa);
    }

    size_t ni = (size_t)n * DH2 + ln;
    float4 e0 = ((const float4*)embeds)[ni];
    uint2 u1 = g_c1[ni];
    uint2 u2 = g_c2[ni];
    float2 c1a = __half22float2(*(const __half2*)&u1.x);
    float2 c1b = __half22float2(*(const __half2*)&u1.y);
    float2 c2a = __half22float2(*(const __half2*)&u2.x);
    float2 c2b = __half22float2(*(const __half2*)&u2.y);

    float4 o;
    o.x = 0.25f * (e0.x + c1a.x + c2a.x + s01.x);
    o.y = 0.25f * (e0.y + c1a.y + c2a.y + s01.y);
    o.z = 0.25f * (e0.z + c1b.x + c2b.x + s23.x);
    o.w = 0.25f * (e0.w + c1b.y + c2b.y + s23.y);
    out[(size_t)row * DH2 + ln] = o;
}

// ---------------- launch -----------------------------------------------------
extern "C" void kernel_launch(void* const* d_in, const int* in_sizes, int n_in,
                              void* d_out, int out_size) {
    const float* embeds = (const float*)d_in[0];
    const float* vals   = (const float*)d_in[1];
    const int*   rows   = (const int*)d_in[2];
    const int*   cols   = (const int*)d_in[3];
    const int*   users  = (const int*)d_in[4];
    const int*   pos    = (const int*)d_in[5];
    const int*   neg    = (const int*)d_in[6];
    const int E  = in_sizes[1];
    const int E2 = E >> 1;
    const int B  = in_sizes[4];
    float4* out = (float4*)d_out;

    init_kernel<<<(N_ITEMS + N_USERS + 255) / 256, 256>>>(rows, E2);
    convert_kernel<<<(N_NODES * DH2 + 255) / 256, 256>>>(embeds);
    hist_pack_kernel<<<(E + 255) / 256, 256>>>(rows, cols, vals, E);
    scanA_kernel<<<SCAN_NB, SCAN_BLK>>>();
    scanB_kernel<<<1, 32>>>(E2);
    scanC_kernel<<<(N_ITEMS / 4 + 255) / 256, 256>>>();
    scatter_kernel<<<(E2 + 255) / 256, 256>>>(rows, cols, vals, E);

    const int spmm_blocks = (N_NODES * 16 + 255) / 256;
    spmm_kernel<0><<<spmm_blocks, 256>>>();
    spmm_kernel<1><<<spmm_blocks, 256>>>();

    final_kernel<<<(3 * B * 16 + 255) / 256, 256>>>(embeds, users, pos, neg, out, B);
}

// round 7
// speedup vs baseline: 1.1653x; 1.1653x over previous
#include <cuda_runtime.h>
#include <cuda_fp16.h>
#include <cstdint>

#define N_USERS 100000
#define N_ITEMS 50000
#define N_NODES (N_USERS + N_ITEMS)   // 150000
#define D 64
#define DH4 (D / 8)                   // 8 uint4 (8 halves each) per row
#define MAX_E 4000000

#define SCAN_BLK  1024
#define SCAN_TILE (SCAN_BLK * 4)                           // 4096
#define SCAN_NB   ((N_ITEMS + SCAN_TILE - 1) / SCAN_TILE)  // 13

// ---------------- static device scratch -------------------------------------
__device__ int   g_count[(N_ITEMS + 3) & ~3];
__device__ int   g_wcur [N_ITEMS];
__device__ int   g_ptr  [N_NODES + 1];
__device__ int   g_bsum [SCAN_NB];
__device__ int2  g_edge [MAX_E];                       // {col, val bits}
__device__ uint4 g_emb_h[(size_t)N_NODES * DH4];       // embeds as fp16
__device__ uint4 g_c1   [(size_t)N_NODES * DH4];       // layer-1 out (fp16)
__device__ uint4 g_c2   [(size_t)N_NODES * DH4];       // layer-2 out (fp16)

// ---------------- step 1: zero counts + user ptrs + fp16 convert (fused) ----
__global__ void init_convert_kernel(const float* __restrict__ embeds,
                                    const int* __restrict__ rows, int E2) {
    int idx = blockIdx.x * blockDim.x + threadIdx.x;

    // role A: convert embeds -> fp16 (one uint4 = 8 halves = 2 float4 reads)
    if (idx < N_NODES * DH4) {
        const float4* e4 = (const float4*)embeds;
        float4 f0 = e4[2 * idx];
        float4 f1 = e4[2 * idx + 1];
        __half2 h0 = __floats2half2_rn(f0.x, f0.y);
        __half2 h1 = __floats2half2_rn(f0.z, f0.w);
        __half2 h2 = __floats2half2_rn(f1.x, f1.y);
        __half2 h3 = __floats2half2_rn(f1.z, f1.w);
        uint4 u;
        u.x = *(const unsigned*)&h0;
        u.y = *(const unsigned*)&h1;
        u.z = *(const unsigned*)&h2;
        u.w = *(const unsigned*)&h3;
        g_emb_h[idx] = u;
    }
    // role B: zero item counters
    if (idx < N_ITEMS) g_count[idx] = 0;
    // role C: user CSR ptrs via binary search over sorted rows[0:E2]
    int r = idx - N_ITEMS;
    if (r >= 0 && r < N_USERS) {
        int lo = 0, hi = E2;
        while (lo < hi) {
            int m = (lo + hi) >> 1;
            if (rows[m] < r) lo = m + 1; else hi = m;
        }
        g_ptr[r] = lo;
    }
}

// ---------------- step 2: pack user-half edges + histogram item degrees -----
// Item half of the edge list is a role-swap of the user half, so this pass
// reads ONLY cols[0:E2] and vals[0:E2].
__global__ void hist_pack_kernel(const int* __restrict__ cols,
                                 const float* __restrict__ vals, int E2) {
    int i = blockIdx.x * blockDim.x + threadIdx.x;
    if (i >= E2) return;
    int c = cols[i];                       // = item + N_USERS
    g_edge[i] = make_int2(c, __float_as_int(vals[i]));
    atomicAdd(&g_count[c - N_USERS], 1);
}

// ---------------- step 3a: per-block local exclusive scan -------------------
__global__ void scanA_kernel() {
    __shared__ int wsum[32];
    const int tid  = threadIdx.x;
    const int lane = tid & 31;
    const int wid  = tid >> 5;
    int base = blockIdx.x * SCAN_TILE + tid * 4;

    int4 v = make_int4(0, 0, 0, 0);
    if (base < N_ITEMS) v = *(const int4*)&g_count[base];
    if (base >= N_ITEMS)     v.x = 0;
    if (base + 1 >= N_ITEMS) v.y = 0;
    if (base + 2 >= N_ITEMS) v.z = 0;
    if (base + 3 >= N_ITEMS) v.w = 0;

    int t = v.x + v.y + v.z + v.w;
    int x = t;
    #pragma unroll
    for (int o = 1; o < 32; o <<= 1) {
        int y = __shfl_up_sync(0xffffffffu, x, o);
        if (lane >= o) x += y;
    }
    if (lane == 31) wsum[wid] = x;
    __syncthreads();
    if (wid == 0) {
        int w = wsum[lane];
        int xs = w;
        #pragma unroll
        for (int o = 1; o < 32; o <<= 1) {
            int y = __shfl_up_sync(0xffffffffu, xs, o);
            if (lane >= o) xs += y;
        }
        wsum[lane] = xs - w;
    }
    __syncthreads();
    int excl = (x - t) + wsum[wid];

    int e0 = excl;
    int e1 = e0 + v.x;
    int e2 = e1 + v.y;
    int e3 = e2 + v.z;
    if (base < N_ITEMS) {
        int lim = N_ITEMS - base;
        int* p = &g_ptr[N_USERS + base];
        if (lim > 0) p[0] = e0;
        if (lim > 1) p[1] = e1;
        if (lim > 2) p[2] = e2;
        if (lim > 3) p[3] = e3;
    }
    if (tid == SCAN_BLK - 1) g_bsum[blockIdx.x] = e3 + v.w;
}

// ---------------- step 3b: scan block totals (one warp) ---------------------
__global__ void scanB_kernel(int E2) {
    int lane = threadIdx.x;
    int v = (lane < SCAN_NB) ? g_bsum[lane] : 0;
    int x = v;
    #pragma unroll
    for (int o = 1; o < 32; o <<= 1) {
        int y = __shfl_up_sync(0xffffffffu, x, o);
        if (lane >= o) x += y;
    }
    if (lane < SCAN_NB) g_bsum[lane] = E2 + (x - v);
    if (lane == 31) g_ptr[N_NODES] = E2 + x;
}

// ---------------- step 3c: apply block offsets + mirror to wcur -------------
__global__ void scanC_kernel() {
    int i4 = (blockIdx.x * blockDim.x + threadIdx.x) * 4;
    if (i4 >= N_ITEMS) return;
    int off = g_bsum[i4 / SCAN_TILE];
    int lim = N_ITEMS - i4;
    int* p = &g_ptr[N_USERS + i4];
    #pragma unroll
    for (int k = 0; k < 4; k++) {
        if (k < lim) {
            int val = p[k] + off;
            p[k] = val;
            g_wcur[i4 + k] = val;
        }
    }
}

// ---------------- step 4: scatter item-half edges ---------------------------
// Payload derived from rows[0:E2] (=u) and the L2-hot g_edge[0:E2].
__global__ void scatter_kernel(const int* __restrict__ rows, int E2) {
    int k = blockIdx.x * blockDim.x + threadIdx.x;
    if (k >= E2) return;
    int2 fe = g_edge[k];                       // {item + N_USERS, val bits}
    int p = atomicAdd(&g_wcur[fe.x - N_USERS], 1);
    g_edge[p] = make_int2(rows[k], fe.y);      // {user, val bits}
}

// ---------------- SpMM (fp16 src -> fp32 accum -> fp16 dst) -----------------
// 8 lanes per destination node; lane owns one uint4 (8 halves) of the row.
__device__ __forceinline__ void fma8(float* s, float v, uint4 x) {
    float2 f0 = __half22float2(*(const __half2*)&x.x);
    float2 f1 = __half22float2(*(const __half2*)&x.y);
    float2 f2 = __half22float2(*(const __half2*)&x.z);
    float2 f3 = __half22float2(*(const __half2*)&x.w);
    s[0] += v * f0.x; s[1] += v * f0.y;
    s[2] += v * f1.x; s[3] += v * f1.y;
    s[4] += v * f2.x; s[5] += v * f2.y;
    s[6] += v * f3.x; s[7] += v * f3.y;
}

__device__ __forceinline__ uint4 pack8(const float* s) {
    __half2 h0 = __floats2half2_rn(s[0], s[1]);
    __half2 h1 = __floats2half2_rn(s[2], s[3]);
    __half2 h2 = __floats2half2_rn(s[4], s[5]);
    __half2 h3 = __floats2half2_rn(s[6], s[7]);
    uint4 u;
    u.x = *(const unsigned*)&h0;
    u.y = *(const unsigned*)&h1;
    u.z = *(const unsigned*)&h2;
    u.w = *(const unsigned*)&h3;
    return u;
}

template <int LAYER>   // 0: emb_h -> c1,  1: c1 -> c2
__global__ void spmm_kernel() {
    int node = (blockIdx.x * blockDim.x + threadIdx.x) >> 3;
    int ln   = threadIdx.x & 7;
    if (node >= N_NODES) return;

    const uint4* __restrict__ src = (LAYER == 0) ? g_emb_h : g_c1;
    uint4* __restrict__ dst       = (LAYER == 0) ? g_c1    : g_c2;

    int beg = g_ptr[node];
    int end = g_ptr[node + 1];

    float s[8] = {0.f, 0.f, 0.f, 0.f, 0.f, 0.f, 0.f, 0.f};
    int e = beg;
    // 4-way unroll: 4 independent gathers in flight per thread
    for (; e + 3 < end; e += 4) {
        int2 a = g_edge[e];
        int2 b = g_edge[e + 1];
        int2 c = g_edge[e + 2];
        int2 d = g_edge[e + 3];
        uint4 xa = src[(size_t)a.x * DH4 + ln];
        uint4 xb = src[(size_t)b.x * DH4 + ln];
        uint4 xc = src[(size_t)c.x * DH4 + ln];
        uint4 xd = src[(size_t)d.x * DH4 + ln];
        fma8(s, __int_as_float(a.y), xa);
        fma8(s, __int_as_float(b.y), xb);
        fma8(s, __int_as_float(c.y), xc);
        fma8(s, __int_as_float(d.y), xd);
    }
    for (; e < end; e++) {
        int2 a = g_edge[e];
        uint4 xa = src[(size_t)a.x * DH4 + ln];
        fma8(s, __int_as_float(a.y), xa);
    }

    dst[(size_t)node * DH4 + ln] = pack8(s);
}

// ---------------- fused layer-3 SpMM + final gather -------------------------
__global__ void final_kernel(const float* __restrict__ embeds,
                             const int* __restrict__ users,
                             const int* __restrict__ pos,
                             const int* __restrict__ neg,
                             float4* __restrict__ out, int B) {
    int row = (blockIdx.x * blockDim.x + threadIdx.x) >> 3;
    int ln  = threadIdx.x & 7;
    if (row >= 3 * B) return;
    int grp = row / B;
    int r   = row - grp * B;
    int n;
    if (grp == 0)      n = users[r];
    else if (grp == 1) n = pos[r] + N_USERS;
    else               n = neg[r] + N_USERS;

    int beg = g_ptr[n];
    int end = g_ptr[n + 1];
    float s[8] = {0.f, 0.f, 0.f, 0.f, 0.f, 0.f, 0.f, 0.f};
    int e = beg;
    for (; e + 3 < end; e += 4) {
        int2 a = g_edge[e];
        int2 b = g_edge[e + 1];
        int2 c = g_edge[e + 2];
        int2 d = g_edge[e + 3];
        uint4 xa = g_c2[(size_t)a.x * DH4 + ln];
        uint4 xb = g_c2[(size_t)b.x * DH4 + ln];
        uint4 xc = g_c2[(size_t)c.x * DH4 + ln];
        uint4 xd = g_c2[(size_t)d.x * DH4 + ln];
        fma8(s, __int_as_float(a.y), xa);
        fma8(s, __int_as_float(b.y), xb);
        fma8(s, __int_as_float(c.y), xc);
        fma8(s, __int_as_float(d.y), xd);
    }
    for (; e < end; e++) {
        int2 a = g_edge[e];
        uint4 xa = g_c2[(size_t)a.x * DH4 + ln];
        fma8(s, __int_as_float(a.y), xa);
    }

    size_t ni = (size_t)n * DH4 + ln;
    const float4* e4 = (const float4*)embeds;
    float4 f0 = e4[2 * ni];
    float4 f1 = e4[2 * ni + 1];
    uint4 u1 = g_c1[ni];
    uint4 u2 = g_c2[ni];

    float c1f[8], c2f[8];
    {
        float2 a0 = __half22float2(*(const __half2*)&u1.x);
        float2 a1 = __half22float2(*(const __half2*)&u1.y);
        float2 a2 = __half22float2(*(const __half2*)&u1.z);
        float2 a3 = __half22float2(*(const __half2*)&u1.w);
        c1f[0]=a0.x; c1f[1]=a0.y; c1f[2]=a1.x; c1f[3]=a1.y;
        c1f[4]=a2.x; c1f[5]=a2.y; c1f[6]=a3.x; c1f[7]=a3.y;
        float2 b0 = __half22float2(*(const __half2*)&u2.x);
        float2 b1 = __half22float2(*(const __half2*)&u2.y);
        float2 b2 = __half22float2(*(const __half2*)&u2.z);
        float2 b3 = __half22float2(*(const __half2*)&u2.w);
        c2f[0]=b0.x; c2f[1]=b0.y; c2f[2]=b1.x; c2f[3]=b1.y;
        c2f[4]=b2.x; c2f[5]=b2.y; c2f[6]=b3.x; c2f[7]=b3.y;
    }

    float4 o0, o1;
    o0.x = 0.25f * (f0.x + c1f[0] + c2f[0] + s[0]);
    o0.y = 0.25f * (f0.y + c1f[1] + c2f[1] + s[1]);
    o0.z = 0.25f * (f0.z + c1f[2] + c2f[2] + s[2]);
    o0.w = 0.25f * (f0.w + c1f[3] + c2f[3] + s[3]);
    o1.x = 0.25f * (f1.x + c1f[4] + c2f[4] + s[4]);
    o1.y = 0.25f * (f1.y + c1f[5] + c2f[5] + s[5]);
    o1.z = 0.25f * (f1.z + c1f[6] + c2f[6] + s[6]);
    o1.w = 0.25f * (f1.w + c1f[7] + c2f[7] + s[7]);
    size_t oi = (size_t)row * DH4 + ln;
    out[2 * oi]     = o0;
    out[2 * oi + 1] = o1;
}

// ---------------- launch -----------------------------------------------------
extern "C" void kernel_launch(void* const* d_in, const int* in_sizes, int n_in,
                              void* d_out, int out_size) {
    const float* embeds = (const float*)d_in[0];
    const int*   rows   = (const int*)d_in[2];
    const int*   cols   = (const int*)d_in[3];
    const float* vals   = (const float*)d_in[1];
    const int*   users  = (const int*)d_in[4];
    const int*   pos    = (const int*)d_in[5];
    const int*   neg    = (const int*)d_in[6];
    const int E  = in_sizes[1];
    const int E2 = E >> 1;
    const int B  = in_sizes[4];
    float4* out = (float4*)d_out;

    init_convert_kernel<<<(N_NODES * DH4 + 255) / 256, 256>>>(embeds, rows, E2);
    hist_pack_kernel<<<(E2 + 255) / 256, 256>>>(cols, vals, E2);
    scanA_kernel<<<SCAN_NB, SCAN_BLK>>>();
    scanB_kernel<<<1, 32>>>(E2);
    scanC_kernel<<<(N_ITEMS / 4 + 255) / 256, 256>>>();
    scatter_kernel<<<(E2 + 255) / 256, 256>>>(rows, E2);

    const int spmm_blocks = (N_NODES * 8 + 255) / 256;
    spmm_kernel<0><<<spmm_blocks, 256>>>();
    spmm_kernel<1><<<spmm_blocks, 256>>>();

    final_kernel<<<(3 * B * 8 + 255) / 256, 256>>>(embeds, users, pos, neg, out, B);
}

// round 8
// speedup vs baseline: 1.2897x; 1.1067x over previous
#include <cuda_runtime.h>
#include <cuda_fp16.h>
#include <cstdint>

#define N_USERS 100000
#define N_ITEMS 50000
#define N_NODES (N_USERS + N_ITEMS)   // 150000
#define D 64
#define DH4 (D / 8)                   // 8 uint4 (8 halves each) per row
#define MAX_E 4000000

#define SCAN_BLK  1024
#define SCAN_TILE (SCAN_BLK * 4)                           // 4096
#define SCAN_NB   ((N_ITEMS + SCAN_TILE - 1) / SCAN_TILE)  // 13

// ---------------- static device scratch -------------------------------------
__device__ int   g_count[(N_ITEMS + 3) & ~3];
__device__ int   g_wcur [N_ITEMS];
__device__ int   g_ptr  [N_NODES + 1];
__device__ int   g_bsum [SCAN_NB];
__device__ int   g_edge [MAX_E];                       // 4B neighbor index only
__device__ uint4 g_t0   [(size_t)N_NODES * DH4];       // inv*emb      (fp16)
__device__ uint4 g_t1   [(size_t)N_NODES * DH4];       // inv*c1       (fp16)
__device__ uint4 g_t2   [(size_t)N_NODES * DH4];       // inv*c2       (fp16)

// ---------------- step 1: zero counts + user ptrs (binary search) -----------
__global__ void init_kernel(const int* __restrict__ rows, int E2) {
    int idx = blockIdx.x * blockDim.x + threadIdx.x;
    if (idx < N_ITEMS) g_count[idx] = 0;
    int r = idx - N_ITEMS;
    if (r >= 0 && r < N_USERS) {
        int lo = 0, hi = E2;
        while (lo < hi) {
            int m = (lo + hi) >> 1;
            if (rows[m] < r) lo = m + 1; else hi = m;
        }
        g_ptr[r] = lo;
    }
}

// ---------------- step 2: pack user-half edges + item histogram -------------
// Only cols[0:E2] is read; item half of inputs is a role-swap and never touched.
__global__ void hist_pack_kernel(const int* __restrict__ cols, int E2) {
    int i = blockIdx.x * blockDim.x + threadIdx.x;
    if (i >= E2) return;
    int c = cols[i];                       // item node id (item + N_USERS)
    g_edge[i] = c;
    atomicAdd(&g_count[c - N_USERS], 1);
}

// ---------------- step 3a: per-block local exclusive scan -------------------
__global__ void scanA_kernel() {
    __shared__ int wsum[32];
    const int tid  = threadIdx.x;
    const int lane = tid & 31;
    const int wid  = tid >> 5;
    int base = blockIdx.x * SCAN_TILE + tid * 4;

    int4 v = make_int4(0, 0, 0, 0);
    if (base < N_ITEMS) v = *(const int4*)&g_count[base];
    if (base >= N_ITEMS)     v.x = 0;
    if (base + 1 >= N_ITEMS) v.y = 0;
    if (base + 2 >= N_ITEMS) v.z = 0;
    if (base + 3 >= N_ITEMS) v.w = 0;

    int t = v.x + v.y + v.z + v.w;
    int x = t;
    #pragma unroll
    for (int o = 1; o < 32; o <<= 1) {
        int y = __shfl_up_sync(0xffffffffu, x, o);
        if (lane >= o) x += y;
    }
    if (lane == 31) wsum[wid] = x;
    __syncthreads();
    if (wid == 0) {
        int w = wsum[lane];
        int xs = w;
        #pragma unroll
        for (int o = 1; o < 32; o <<= 1) {
            int y = __shfl_up_sync(0xffffffffu, xs, o);
            if (lane >= o) xs += y;
        }
        wsum[lane] = xs - w;
    }
    __syncthreads();
    int excl = (x - t) + wsum[wid];

    int e0 = excl;
    int e1 = e0 + v.x;
    int e2 = e1 + v.y;
    int e3 = e2 + v.z;
    if (base < N_ITEMS) {
        int lim = N_ITEMS - base;
        int* p = &g_ptr[N_USERS + base];
        if (lim > 0) p[0] = e0;
        if (lim > 1) p[1] = e1;
        if (lim > 2) p[2] = e2;
        if (lim > 3) p[3] = e3;
    }
    if (tid == SCAN_BLK - 1) g_bsum[blockIdx.x] = e3 + v.w;
}

// ---------------- step 3b: apply tile offsets (scanB folded in) -------------
__global__ void scanC_kernel(int E2) {
    int gid = blockIdx.x * blockDim.x + threadIdx.x;
    int i4 = gid * 4;
    if (gid == 0) {
        int tot = E2;
        #pragma unroll
        for (int j = 0; j < SCAN_NB; j++) tot += g_bsum[j];
        g_ptr[N_NODES] = tot;              // == E
    }
    if (i4 >= N_ITEMS) return;
    int tile = i4 / SCAN_TILE;
    int off = E2;
    for (int j = 0; j < tile; j++) off += g_bsum[j];   // <=12 L2-hot reads
    int lim = N_ITEMS - i4;
    int* p = &g_ptr[N_USERS + i4];
    #pragma unroll
    for (int k = 0; k < 4; k++) {
        if (k < lim) {
            int val = p[k] + off;
            p[k] = val;
            g_wcur[i4 + k] = val;
        }
    }
}

// ---------------- step 4: scatter item-half edges + scaled fp16 convert -----
// scatter payload derived from rows[0:E2] + L2-hot g_edge[0:E2].
// convert: t0[n] = rsqrt(deg(n)) * embeds[n]  (degrees now known from g_ptr).
__global__ void scatter_convert_kernel(const int* __restrict__ rows,
                                       const float* __restrict__ embeds,
                                       int E2) {
    int idx = blockIdx.x * blockDim.x + threadIdx.x;

    if (idx < E2) {
        int c = g_edge[idx];                           // item node id
        int p = atomicAdd(&g_wcur[c - N_USERS], 1);    // p >= E2, no race w/ reads
        g_edge[p] = rows[idx];                         // user node id
    }

    if (idx < N_NODES * DH4) {
        int node = idx >> 3;
        int deg  = g_ptr[node + 1] - g_ptr[node];
        float inv = (deg > 0) ? rsqrtf((float)deg) : 0.f;
        const float4* e4 = (const float4*)embeds;
        float4 f0 = e4[2 * idx];
        float4 f1 = e4[2 * idx + 1];
        __half2 h0 = __floats2half2_rn(inv * f0.x, inv * f0.y);
        __half2 h1 = __floats2half2_rn(inv * f0.z, inv * f0.w);
        __half2 h2 = __floats2half2_rn(inv * f1.x, inv * f1.y);
        __half2 h3 = __floats2half2_rn(inv * f1.z, inv * f1.w);
        uint4 u;
        u.x = *(const unsigned*)&h0;
        u.y = *(const unsigned*)&h1;
        u.z = *(const unsigned*)&h2;
        u.w = *(const unsigned*)&h3;
        g_t0[idx] = u;
    }
}

// ---------------- SpMM helpers -----------------------------------------------
__device__ __forceinline__ void add8(float* s, uint4 x) {
    float2 f0 = __half22float2(*(const __half2*)&x.x);
    float2 f1 = __half22float2(*(const __half2*)&x.y);
    float2 f2 = __half22float2(*(const __half2*)&x.z);
    float2 f3 = __half22float2(*(const __half2*)&x.w);
    s[0] += f0.x; s[1] += f0.y;
    s[2] += f1.x; s[3] += f1.y;
    s[4] += f2.x; s[5] += f2.y;
    s[6] += f3.x; s[7] += f3.y;
}

__device__ __forceinline__ uint4 pack8s(const float* s, float w) {
    __half2 h0 = __floats2half2_rn(w * s[0], w * s[1]);
    __half2 h1 = __floats2half2_rn(w * s[2], w * s[3]);
    __half2 h2 = __floats2half2_rn(w * s[4], w * s[5]);
    __half2 h3 = __floats2half2_rn(w * s[6], w * s[7]);
    uint4 u;
    u.x = *(const unsigned*)&h0;
    u.y = *(const unsigned*)&h1;
    u.z = *(const unsigned*)&h2;
    u.w = *(const unsigned*)&h3;
    return u;
}

// ---------------- SpMM: t_{k+1}[n] = (sum_{c in N(n)} t_k[c]) / deg(n) ------
template <int LAYER>   // 0: t0 -> t1,  1: t1 -> t2
__global__ void spmm_kernel() {
    int node = (blockIdx.x * blockDim.x + threadIdx.x) >> 3;
    int ln   = threadIdx.x & 7;
    if (node >= N_NODES) return;

    const uint4* __restrict__ src = (LAYER == 0) ? g_t0 : g_t1;
    uint4* __restrict__ dst       = (LAYER == 0) ? g_t1 : g_t2;

    int beg = g_ptr[node];
    int end = g_ptr[node + 1];

    float s[8] = {0.f, 0.f, 0.f, 0.f, 0.f, 0.f, 0.f, 0.f};
    int e = beg;
    for (; e + 3 < end; e += 4) {
        int a = g_edge[e];
        int b = g_edge[e + 1];
        int c = g_edge[e + 2];
        int d = g_edge[e + 3];
        uint4 xa = src[(size_t)a * DH4 + ln];
        uint4 xb = src[(size_t)b * DH4 + ln];
        uint4 xc = src[(size_t)c * DH4 + ln];
        uint4 xd = src[(size_t)d * DH4 + ln];
        add8(s, xa); add8(s, xb); add8(s, xc); add8(s, xd);
    }
    for (; e < end; e++) {
        uint4 xa = src[(size_t)g_edge[e] * DH4 + ln];
        add8(s, xa);
    }

    int deg = end - beg;
    float w = (deg > 0) ? (1.f / (float)deg) : 0.f;
    dst[(size_t)node * DH4 + ln] = pack8s(s, w);
}

// ---------------- fused layer-3 SpMM + final gather -------------------------
// out = 0.25 * ( emb[n] + (t1[n]+t2[n])*sqrt(deg) + rsqrt(deg)*sum_c t2[c] )
__global__ void final_kernel(const float* __restrict__ embeds,
                             const int* __restrict__ users,
                             const int* __restrict__ pos,
                             const int* __restrict__ neg,
                             float4* __restrict__ out, int B) {
    int row = (blockIdx.x * blockDim.x + threadIdx.x) >> 3;
    int ln  = threadIdx.x & 7;
    if (row >= 3 * B) return;
    int grp = row / B;
    int r   = row - grp * B;
    int n;
    if (grp == 0)      n = users[r];
    else if (grp == 1) n = pos[r] + N_USERS;
    else               n = neg[r] + N_USERS;

    int beg = g_ptr[n];
    int end = g_ptr[n + 1];
    float s[8] = {0.f, 0.f, 0.f, 0.f, 0.f, 0.f, 0.f, 0.f};
    int e = beg;
    for (; e + 3 < end; e += 4) {
        int a = g_edge[e];
        int b = g_edge[e + 1];
        int c = g_edge[e + 2];
        int d = g_edge[e + 3];
        uint4 xa = g_t2[(size_t)a * DH4 + ln];
        uint4 xb = g_t2[(size_t)b * DH4 + ln];
        uint4 xc = g_t2[(size_t)c * DH4 + ln];
        uint4 xd = g_t2[(size_t)d * DH4 + ln];
        add8(s, xa); add8(s, xb); add8(s, xc); add8(s, xd);
    }
    for (; e < end; e++) {
        uint4 xa = g_t2[(size_t)g_edge[e] * DH4 + ln];
        add8(s, xa);
    }

    int deg = end - beg;
    float sq  = (deg > 0) ? sqrtf((float)deg)  : 0.f;
    float inv = (deg > 0) ? rsqrtf((float)deg) : 0.f;

    size_t ni = (size_t)n * DH4 + ln;
    const float4* e4 = (const float4*)embeds;
    float4 f0 = e4[2 * ni];
    float4 f1 = e4[2 * ni + 1];
    uint4 u1 = g_t1[ni];
    uint4 u2 = g_t2[ni];

    float tf[8];
    {
        float2 a0 = __half22float2(*(const __half2*)&u1.x);
        float2 a1 = __half22float2(*(const __half2*)&u1.y);
        float2 a2 = __half22float2(*(const __half2*)&u1.z);
        float2 a3 = __half22float2(*(const __half2*)&u1.w);
        float2 b0 = __half22float2(*(const __half2*)&u2.x);
        float2 b1 = __half22float2(*(const __half2*)&u2.y);
        float2 b2 = __half22float2(*(const __half2*)&u2.z);
        float2 b3 = __half22float2(*(const __half2*)&u2.w);
        tf[0] = a0.x + b0.x; tf[1] = a0.y + b0.y;
        tf[2] = a1.x + b1.x; tf[3] = a1.y + b1.y;
        tf[4] = a2.x + b2.x; tf[5] = a2.y + b2.y;
        tf[6] = a3.x + b3.x; tf[7] = a3.y + b3.y;
    }

    float4 o0, o1;
    o0.x = 0.25f * (f0.x + tf[0] * sq + s[0] * inv);
    o0.y = 0.25f * (f0.y + tf[1] * sq + s[1] * inv);
    o0.z = 0.25f * (f0.z + tf[2] * sq + s[2] * inv);
    o0.w = 0.25f * (f0.w + tf[3] * sq + s[3] * inv);
    o1.x = 0.25f * (f1.x + tf[4] * sq + s[4] * inv);
    o1.y = 0.25f * (f1.y + tf[5] * sq + s[5] * inv);
    o1.z = 0.25f * (f1.z + tf[6] * sq + s[6] * inv);
    o1.w = 0.25f * (f1.w + tf[7] * sq + s[7] * inv);
    size_t oi = (size_t)row * DH4 + ln;
    out[2 * oi]     = o0;
    out[2 * oi + 1] = o1;
}

// ---------------- launch -----------------------------------------------------
extern "C" void kernel_launch(void* const* d_in, const int* in_sizes, int n_in,
                              void* d_out, int out_size) {
    const float* embeds = (const float*)d_in[0];
    const int*   rows   = (const int*)d_in[2];
    const int*   cols   = (const int*)d_in[3];
    const int*   users  = (const int*)d_in[4];
    const int*   pos    = (const int*)d_in[5];
    const int*   neg    = (const int*)d_in[6];
    const int E  = in_sizes[1];
    const int E2 = E >> 1;
    const int B  = in_sizes[4];
    float4* out = (float4*)d_out;

    init_kernel<<<(N_ITEMS + N_USERS + 255) / 256, 256>>>(rows, E2);
    hist_pack_kernel<<<(E2 + 255) / 256, 256>>>(cols, E2);
    scanA_kernel<<<SCAN_NB, SCAN_BLK>>>();
    scanC_kernel<<<(N_ITEMS / 4 + 256) / 256, 256>>>(E2);

    int sc_threads = (E2 > N_NODES * DH4) ? E2 : N_NODES * DH4;
    scatter_convert_kernel<<<(sc_threads + 255) / 256, 256>>>(rows, embeds, E2);

    const int spmm_blocks = (N_NODES * 8 + 255) / 256;
    spmm_kernel<0><<<spmm_blocks, 256>>>();
    spmm_kernel<1><<<spmm_blocks, 256>>>();

    final_kernel<<<(3 * B * 8 + 255) / 256, 256>>>(embeds, users, pos, neg, out, B);
}